// round 2
// baseline (speedup 1.0000x reference)
#include <cuda_runtime.h>
#include <cstdint>
#include <cstddef>

#define Nn 50000
#define Ee 1600000
#define Gg 128
#define Hh 64
#define NEe 5

// ---- scratch (device globals: allocation-free rule) ----
__device__ float g_y[(size_t)NEe * Nn * Hh];   // 64 MB: y_k = act(x) @ W[k]
__device__ float g_h0[(size_t)Nn * Hh];        // ping
__device__ float g_h1[(size_t)Nn * Hh];        // pong
__device__ float g_pool[Gg * 2 * Hh];

// sort scratch
__device__ int    g_cnt[Nn];
__device__ int    g_cursor[Nn];
__device__ int    g_ssrc[Ee];
__device__ int    g_sdst[Ee];
__device__ float4 g_sea4[Ee];
__device__ float  g_sea1[Ee];

// ============================================================
// counting sort by src: hist -> scan -> permute
// ============================================================
__global__ void zero_cnt_kernel(int* __restrict__ cnt)
{
    unsigned i = blockIdx.x * 256u + threadIdx.x;
    if (i < (unsigned)Nn) cnt[i] = 0;
}

__global__ void hist_kernel(const int* __restrict__ ei, int* __restrict__ cnt)
{
    unsigned e = blockIdx.x * 256u + threadIdx.x;
    if (e < (unsigned)Ee) atomicAdd(&cnt[__ldg(ei + e)], 1);
}

// one block, 1024 threads: exclusive prefix over 50K counts
__global__ void scan_kernel(const int* __restrict__ cnt,
                            int* __restrict__ cursor)
{
    __shared__ int tsum[1024];
    const int t  = threadIdx.x;
    const int CH = (Nn + 1023) / 1024;  // 49
    const int base = t * CH;

    int s = 0;
#pragma unroll 1
    for (int i = 0; i < CH; ++i) {
        int idx = base + i;
        if (idx < Nn) s += cnt[idx];
    }
    tsum[t] = s;
    __syncthreads();
    // inclusive Hillis-Steele scan over 1024 thread sums
    for (int o = 1; o < 1024; o <<= 1) {
        int u = (t >= o) ? tsum[t - o] : 0;
        __syncthreads();
        tsum[t] += u;
        __syncthreads();
    }
    int run = tsum[t] - s;  // exclusive
#pragma unroll 1
    for (int i = 0; i < CH; ++i) {
        int idx = base + i;
        if (idx < Nn) {
            cursor[idx] = run;
            run += cnt[idx];
        }
    }
}

__global__ void permute_kernel(const int* __restrict__ ei,
                               const float* __restrict__ ea,
                               int* __restrict__ cursor,
                               int* __restrict__ ssrc,
                               int* __restrict__ sdst,
                               float4* __restrict__ sea4,
                               float* __restrict__ sea1)
{
    unsigned e = blockIdx.x * 256u + threadIdx.x;
    if (e >= (unsigned)Ee) return;
    int src = __ldg(ei + e);
    int pos = atomicAdd(&cursor[src], 1);
    ssrc[pos] = src;
    sdst[pos] = __ldg(ei + Ee + e);
    const float* p = ea + (size_t)e * 5;
    sea4[pos] = make_float4(__ldg(p), __ldg(p + 1), __ldg(p + 2), __ldg(p + 3));
    sea1[pos] = __ldg(p + 4);
}

// ============================================================
// GEMM: y[k][n][0:64] = act(in[n][0:KD]) @ W[k], one (node-tile, k) per CTA
// ============================================================
template<int KD>
__global__ void gemm1_kernel(const float* __restrict__ in,
                             const float* __restrict__ W,
                             float* __restrict__ y,
                             int relu_in)
{
    __shared__ float xsT[KD][68];
    __shared__ float ws[KD * 64];
    const int t  = threadIdx.x;
    const int n0 = blockIdx.x * 64;
    const int k  = blockIdx.y;

    for (int idx = t; idx < 64 * KD; idx += 256) {
        int node = idx / KD;
        int c    = idx - node * KD;
        int n    = n0 + node;
        float v  = (n < Nn) ? in[(size_t)n * KD + c] : 0.f;
        if (relu_in) v = fmaxf(v, 0.f);
        xsT[c][node] = v;
    }
    for (int idx = t; idx < KD * 64; idx += 256)
        ws[idx] = __ldg(W + k * KD * 64 + idx);
    __syncthreads();

    const int tx = t & 15;
    const int ty = t >> 4;

    float4 acc0 = {0.f,0.f,0.f,0.f}, acc1 = acc0, acc2 = acc0, acc3 = acc0;
#pragma unroll
    for (int kk = 0; kk < KD; ++kk) {
        float4 xv = *(const float4*)&xsT[kk][ty * 4];
        float4 wv = *(const float4*)&ws[kk * 64 + tx * 4];
        acc0.x += xv.x * wv.x; acc0.y += xv.x * wv.y; acc0.z += xv.x * wv.z; acc0.w += xv.x * wv.w;
        acc1.x += xv.y * wv.x; acc1.y += xv.y * wv.y; acc1.z += xv.y * wv.z; acc1.w += xv.y * wv.w;
        acc2.x += xv.z * wv.x; acc2.y += xv.z * wv.y; acc2.z += xv.z * wv.z; acc2.w += xv.z * wv.w;
        acc3.x += xv.w * wv.x; acc3.y += xv.w * wv.y; acc3.z += xv.w * wv.z; acc3.w += xv.w * wv.w;
    }

    float* yk = y + (size_t)k * Nn * Hh;
    int nl = n0 + ty * 4;
    if (nl + 0 < Nn) *(float4*)&yk[(size_t)(nl + 0) * 64 + tx * 4] = acc0;
    if (nl + 1 < Nn) *(float4*)&yk[(size_t)(nl + 1) * 64 + tx * 4] = acc1;
    if (nl + 2 < Nn) *(float4*)&yk[(size_t)(nl + 2) * 64 + tx * 4] = acc2;
    if (nl + 3 < Nn) *(float4*)&yk[(size_t)(nl + 3) * 64 + tx * 4] = acc3;
}

// ============================================================
// h[n][f] = b[f]
// ============================================================
__global__ void init_bias_kernel(float* __restrict__ h, const float* __restrict__ b)
{
    unsigned i = blockIdx.x * 256u + threadIdx.x;
    if (i < (unsigned)(Nn * 64)) h[i] = __ldg(b + (i & 63u));
}

// ============================================================
// Edge scatter on src-sorted edges: h[dst] += sum_k ea[k] * y[k][src]
// ============================================================
__global__ void scatter_kernel(const int* __restrict__ ssrc,
                               const int* __restrict__ sdst,
                               const float4* __restrict__ sea4,
                               const float* __restrict__ sea1,
                               const float* __restrict__ y,
                               float* __restrict__ h)
{
    unsigned idx = blockIdx.x * 256u + threadIdx.x;
    unsigned e   = idx >> 4;
    unsigned li  = idx & 15u;
    if (e >= (unsigned)Ee) return;

    int src = __ldg(ssrc + e);
    int dst = __ldg(sdst + e);
    float4 w = __ldg(sea4 + e);
    float w4 = __ldg(sea1 + e);

    const size_t KS = (size_t)Nn * 64;
    const float* yp = y + (size_t)src * 64 + li * 4;
    float4 v0 = __ldg((const float4*)(yp));
    float4 v1 = __ldg((const float4*)(yp + KS));
    float4 v2 = __ldg((const float4*)(yp + 2 * KS));
    float4 v3 = __ldg((const float4*)(yp + 3 * KS));
    float4 v4 = __ldg((const float4*)(yp + 4 * KS));

    float ax = w.x*v0.x + w.y*v1.x + w.z*v2.x + w.w*v3.x + w4*v4.x;
    float ay = w.x*v0.y + w.y*v1.y + w.z*v2.y + w.w*v3.y + w4*v4.y;
    float az = w.x*v0.z + w.y*v1.z + w.z*v2.z + w.w*v3.z + w4*v4.z;
    float aw = w.x*v0.w + w.y*v1.w + w.z*v2.w + w.w*v3.w + w4*v4.w;

    float* hp = h + (size_t)dst * 64 + li * 4;
    asm volatile("red.global.add.v4.f32 [%0], {%1,%2,%3,%4};"
                 :: "l"(hp), "f"(ax), "f"(ay), "f"(az), "f"(aw) : "memory");
}

// ============================================================
// Pooling (relu + sum/max per analytic graph ranges)
// ============================================================
__global__ void pool_kernel(const float* __restrict__ h, float* __restrict__ pooled)
{
    __shared__ float ss[4][64];
    __shared__ float sm[4][64];
    int g     = blockIdx.x;
    int f     = threadIdx.x & 63;
    int strip = threadIdx.x >> 6;
    int start = (g * Nn + Gg - 1) / Gg;
    int end   = ((g + 1) * Nn + Gg - 1) / Gg;

    float s = 0.f, m = 0.f;
    for (int n = start + strip; n < end; n += 4) {
        float v = fmaxf(__ldg(h + (size_t)n * 64 + f), 0.f);
        s += v;
        m = fmaxf(m, v);
    }
    ss[strip][f] = s;
    sm[strip][f] = m;
    __syncthreads();
    if (strip == 0) {
        s = ss[0][f] + ss[1][f] + ss[2][f] + ss[3][f];
        m = fmaxf(fmaxf(sm[0][f], sm[1][f]), fmaxf(sm[2][f], sm[3][f]));
        pooled[g * 128 + f]      = s;
        pooled[g * 128 + 64 + f] = m;
    }
}

// ============================================================
// Head: BN -> FC -> log_softmax
// ============================================================
__global__ void head_kernel(const float* __restrict__ pooled,
                            const float* __restrict__ gam,
                            const float* __restrict__ bet,
                            const float* __restrict__ mean,
                            const float* __restrict__ var,
                            const float* __restrict__ fw,
                            const float* __restrict__ fb,
                            float* __restrict__ out)
{
    int g    = blockIdx.x;
    int lane = threadIdx.x;

    float pn[4];
#pragma unroll
    for (int i = 0; i < 4; ++i) {
        int c = lane + 32 * i;
        float p = __ldg(pooled + g * 128 + c);
        float inv = 1.f / sqrtf(__ldg(var + c) + 1e-5f);
        pn[i] = (p - __ldg(mean + c)) * inv * __ldg(gam + c) + __ldg(bet + c);
    }

    float logits[6];
#pragma unroll
    for (int j = 0; j < 6; ++j) {
        float s = 0.f;
#pragma unroll
        for (int i = 0; i < 4; ++i)
            s += pn[i] * __ldg(fw + (lane + 32 * i) * 6 + j);
#pragma unroll
        for (int o = 16; o; o >>= 1)
            s += __shfl_xor_sync(0xffffffffu, s, o);
        logits[j] = s + __ldg(fb + j);
    }

    if (lane == 0) {
        float m = logits[0];
#pragma unroll
        for (int j = 1; j < 6; ++j) m = fmaxf(m, logits[j]);
        float se = 0.f;
#pragma unroll
        for (int j = 0; j < 6; ++j) se += expf(logits[j] - m);
        float lse = m + logf(se);
#pragma unroll
        for (int j = 0; j < 6; ++j) out[g * 6 + j] = logits[j] - lse;
    }
}

// ============================================================
extern "C" void kernel_launch(void* const* d_in, const int* in_sizes, int n_in,
                              void* d_out, int out_size)
{
    const float* x   = (const float*)d_in[0];
    const int*   ei  = (const int*)  d_in[1];
    const float* ea  = (const float*)d_in[2];
    const float* W1  = (const float*)d_in[4];
    const float* b1  = (const float*)d_in[5];
    const float* W2  = (const float*)d_in[6];
    const float* b2  = (const float*)d_in[7];
    const float* W3  = (const float*)d_in[8];
    const float* b3  = (const float*)d_in[9];
    const float* W4  = (const float*)d_in[10];
    const float* b4  = (const float*)d_in[11];
    const float* bng = (const float*)d_in[12];
    const float* bnb = (const float*)d_in[13];
    const float* bnm = (const float*)d_in[14];
    const float* bnv = (const float*)d_in[15];
    const float* fw  = (const float*)d_in[16];
    const float* fb  = (const float*)d_in[17];
    float* out = (float*)d_out;

    float *yb, *h0, *h1, *pl, *sea1p;
    int *cnt, *cur, *ssrc, *sdst;
    float4* sea4p;
    cudaGetSymbolAddress((void**)&yb, g_y);
    cudaGetSymbolAddress((void**)&h0, g_h0);
    cudaGetSymbolAddress((void**)&h1, g_h1);
    cudaGetSymbolAddress((void**)&pl, g_pool);
    cudaGetSymbolAddress((void**)&cnt, g_cnt);
    cudaGetSymbolAddress((void**)&cur, g_cursor);
    cudaGetSymbolAddress((void**)&ssrc, g_ssrc);
    cudaGetSymbolAddress((void**)&sdst, g_sdst);
    cudaGetSymbolAddress((void**)&sea4p, g_sea4);
    cudaGetSymbolAddress((void**)&sea1p, g_sea1);

    const int EB = (Ee + 255) / 256;      // 6250
    const int GB = (Nn + 63) / 64;        // 782
    const int IB = (Nn * 64 + 255) / 256; // 12500
    const int SB = (Ee * 16) / 256;       // 100000

    // ---- counting sort of edges by src ----
    zero_cnt_kernel<<<(Nn + 255) / 256, 256>>>(cnt);
    hist_kernel<<<EB, 256>>>(ei, cnt);
    scan_kernel<<<1, 1024>>>(cnt, cur);
    permute_kernel<<<EB, 256>>>(ei, ea, cur, ssrc, sdst, sea4p, sea1p);

    // ---- layer 1 (in: x [N,16]) ----
    gemm1_kernel<16><<<dim3(GB, 5), 256>>>(x, W1, yb, 0);
    init_bias_kernel<<<IB, 256>>>(h0, b1);
    scatter_kernel<<<SB, 256>>>(ssrc, sdst, sea4p, sea1p, yb, h0);
    // ---- layer 2 ----
    gemm1_kernel<64><<<dim3(GB, 5), 256>>>(h0, W2, yb, 1);
    init_bias_kernel<<<IB, 256>>>(h1, b2);
    scatter_kernel<<<SB, 256>>>(ssrc, sdst, sea4p, sea1p, yb, h1);
    // ---- layer 3 ----
    gemm1_kernel<64><<<dim3(GB, 5), 256>>>(h1, W3, yb, 1);
    init_bias_kernel<<<IB, 256>>>(h0, b3);
    scatter_kernel<<<SB, 256>>>(ssrc, sdst, sea4p, sea1p, yb, h0);
    // ---- layer 4 ----
    gemm1_kernel<64><<<dim3(GB, 5), 256>>>(h0, W4, yb, 1);
    init_bias_kernel<<<IB, 256>>>(h1, b4);
    scatter_kernel<<<SB, 256>>>(ssrc, sdst, sea4p, sea1p, yb, h1);

    pool_kernel<<<Gg, 256>>>(h1, pl);
    head_kernel<<<Gg, 32>>>(pl, bng, bnb, bnm, bnv, fw, fb, out);
}

// round 3
// speedup vs baseline: 1.4839x; 1.4839x over previous
#include <cuda_runtime.h>
#include <cstdint>
#include <cstddef>

#define Nn 50000
#define Ee 1600000
#define Gg 128
#define Hh 64

// ---- scratch (device globals) ----
__device__ float g_z[(size_t)5 * Nn * Hh];     // 64 MB: z_k = segment_sum(ea_k * act(h[src]))
__device__ float g_h0[(size_t)Nn * Hh];        // ping
__device__ float g_h1[(size_t)Nn * Hh];        // pong
__device__ float g_pool[Gg * 2 * Hh];

// dst-CSR sort scratch
__device__ int    g_cnt[Nn];
__device__ int    g_cursor[Nn];
__device__ int    g_rowptr[Nn + 1];
__device__ int    g_ssrc[Ee];
__device__ float4 g_sea4[Ee];
__device__ float  g_sea1[Ee];

// ============================================================
// counting sort by dst: hist -> scan -> permute
// ============================================================
__global__ void zero_cnt_kernel(int* __restrict__ cnt)
{
    unsigned i = blockIdx.x * 256u + threadIdx.x;
    if (i < (unsigned)Nn) cnt[i] = 0;
}

__global__ void hist_kernel(const int* __restrict__ ei, int* __restrict__ cnt)
{
    unsigned e = blockIdx.x * 256u + threadIdx.x;
    if (e < (unsigned)Ee) atomicAdd(&cnt[__ldg(ei + Ee + e)], 1);  // dst
}

// one block, 1024 threads: exclusive prefix over 50K counts -> rowptr & cursor
__global__ void scan_kernel(const int* __restrict__ cnt,
                            int* __restrict__ cursor,
                            int* __restrict__ rowptr)
{
    __shared__ int tsum[1024];
    const int t  = threadIdx.x;
    const int CH = (Nn + 1023) / 1024;  // 49
    const int base = t * CH;

    int s = 0;
#pragma unroll 1
    for (int i = 0; i < CH; ++i) {
        int idx = base + i;
        if (idx < Nn) s += cnt[idx];
    }
    tsum[t] = s;
    __syncthreads();
    for (int o = 1; o < 1024; o <<= 1) {
        int u = (t >= o) ? tsum[t - o] : 0;
        __syncthreads();
        tsum[t] += u;
        __syncthreads();
    }
    int run = tsum[t] - s;  // exclusive
#pragma unroll 1
    for (int i = 0; i < CH; ++i) {
        int idx = base + i;
        if (idx < Nn) {
            cursor[idx] = run;
            rowptr[idx] = run;
            run += cnt[idx];
        }
    }
    if (t == 0) rowptr[Nn] = Ee;
}

__global__ void permute_kernel(const int* __restrict__ ei,
                               const float* __restrict__ ea,
                               int* __restrict__ cursor,
                               int* __restrict__ ssrc,
                               float4* __restrict__ sea4,
                               float* __restrict__ sea1)
{
    unsigned e = blockIdx.x * 256u + threadIdx.x;
    if (e >= (unsigned)Ee) return;
    int src = __ldg(ei + e);
    int dst = __ldg(ei + Ee + e);
    const float* p = ea + (size_t)e * 5;
    float4 w = make_float4(__ldg(p), __ldg(p + 1), __ldg(p + 2), __ldg(p + 3));
    float w4 = __ldg(p + 4);
    int pos = atomicAdd(&cursor[dst], 1);
    ssrc[pos] = src;
    sea4[pos] = w;
    sea1[pos] = w4;
}

// ============================================================
// Aggregate (H=64): one warp per dst node. Lane covers 2 feats.
// z_k[dst] = sum_{e in CSR[dst]} ea[e][k] * act(x[src_e])   (plain stores, no atomics)
// ============================================================
template<int RELU>
__global__ void aggregate64_kernel(const int* __restrict__ rowptr,
                                   const int* __restrict__ ssrc,
                                   const float4* __restrict__ sea4,
                                   const float* __restrict__ sea1,
                                   const float* __restrict__ x,
                                   float* __restrict__ z)
{
    int dst = blockIdx.x * 8 + (threadIdx.x >> 5);
    if (dst >= Nn) return;
    const int lane = threadIdx.x & 31;
    const int beg = __ldg(rowptr + dst);
    const int end = __ldg(rowptr + dst + 1);

    float2 a0 = {0.f,0.f}, a1 = a0, a2 = a0, a3 = a0, a4 = a0;

#pragma unroll 2
    for (int e = beg; e < end; ++e) {
        int   src = __ldg(ssrc + e);
        float4 w  = __ldg(sea4 + e);
        float  w4 = __ldg(sea1 + e);
        float2 v  = __ldg((const float2*)(x + (size_t)src * 64 + lane * 2));
        if (RELU) { v.x = fmaxf(v.x, 0.f); v.y = fmaxf(v.y, 0.f); }
        a0.x += w.x * v.x; a0.y += w.x * v.y;
        a1.x += w.y * v.x; a1.y += w.y * v.y;
        a2.x += w.z * v.x; a2.y += w.z * v.y;
        a3.x += w.w * v.x; a3.y += w.w * v.y;
        a4.x += w4  * v.x; a4.y += w4  * v.y;
    }

    const size_t KS = (size_t)Nn * 64;
    float* zp = z + (size_t)dst * 64 + lane * 2;
    *(float2*)(zp)          = a0;
    *(float2*)(zp + KS)     = a1;
    *(float2*)(zp + 2*KS)   = a2;
    *(float2*)(zp + 3*KS)   = a3;
    *(float2*)(zp + 4*KS)   = a4;
}

// ============================================================
// Aggregate (F=16, layer 1, no relu): warp splits in 2 halves over edges,
// each half covers 16 feats; combine via shfl_xor(16).
// ============================================================
__global__ void aggregate16_kernel(const int* __restrict__ rowptr,
                                   const int* __restrict__ ssrc,
                                   const float4* __restrict__ sea4,
                                   const float* __restrict__ sea1,
                                   const float* __restrict__ x,
                                   float* __restrict__ z)
{
    int dst = blockIdx.x * 8 + (threadIdx.x >> 5);
    if (dst >= Nn) return;
    const int lane = threadIdx.x & 31;
    const int half = lane >> 4;
    const int f    = lane & 15;
    const int beg = __ldg(rowptr + dst);
    const int end = __ldg(rowptr + dst + 1);

    float a0 = 0.f, a1 = 0.f, a2 = 0.f, a3 = 0.f, a4 = 0.f;

    for (int e = beg + half; e < end; e += 2) {
        int   src = __ldg(ssrc + e);
        float4 w  = __ldg(sea4 + e);
        float  w4 = __ldg(sea1 + e);
        float  v  = __ldg(x + (size_t)src * 16 + f);
        a0 += w.x * v; a1 += w.y * v; a2 += w.z * v; a3 += w.w * v; a4 += w4 * v;
    }
    a0 += __shfl_xor_sync(0xffffffffu, a0, 16);
    a1 += __shfl_xor_sync(0xffffffffu, a1, 16);
    a2 += __shfl_xor_sync(0xffffffffu, a2, 16);
    a3 += __shfl_xor_sync(0xffffffffu, a3, 16);
    a4 += __shfl_xor_sync(0xffffffffu, a4, 16);

    if (half == 0) {
        const size_t KS = (size_t)Nn * 16;
        float* zp = z + (size_t)dst * 16 + f;
        zp[0]      = a0;
        zp[KS]     = a1;
        zp[2*KS]   = a2;
        zp[3*KS]   = a3;
        zp[4*KS]   = a4;
    }
}

// ============================================================
// GEMM-sum: h[n] = sum_k z_k[n] @ W[k] + b   (64 nodes x 64 outs / CTA)
// ============================================================
template<int KD>
__global__ void gemmsum_kernel(const float* __restrict__ z,
                               const float* __restrict__ W,
                               const float* __restrict__ b,
                               float* __restrict__ h)
{
    __shared__ float zsT[KD][68];
    __shared__ float ws[KD * 64];
    const int t  = threadIdx.x;
    const int n0 = blockIdx.x * 64;
    const int tx = t & 15;
    const int ty = t >> 4;

    float4 acc0 = {0.f,0.f,0.f,0.f}, acc1 = acc0, acc2 = acc0, acc3 = acc0;

#pragma unroll 1
    for (int k = 0; k < 5; ++k) {
        __syncthreads();
        const float* zk = z + (size_t)k * Nn * KD;
        for (int idx = t; idx < 64 * KD; idx += 256) {
            int node = idx / KD;
            int c    = idx - node * KD;
            int n    = n0 + node;
            zsT[c][node] = (n < Nn) ? zk[(size_t)n * KD + c] : 0.f;
        }
        for (int idx = t; idx < KD * 64; idx += 256)
            ws[idx] = __ldg(W + k * KD * 64 + idx);
        __syncthreads();

#pragma unroll
        for (int kk = 0; kk < KD; ++kk) {
            float4 xv = *(const float4*)&zsT[kk][ty * 4];
            float4 wv = *(const float4*)&ws[kk * 64 + tx * 4];
            acc0.x += xv.x * wv.x; acc0.y += xv.x * wv.y; acc0.z += xv.x * wv.z; acc0.w += xv.x * wv.w;
            acc1.x += xv.y * wv.x; acc1.y += xv.y * wv.y; acc1.z += xv.y * wv.z; acc1.w += xv.y * wv.w;
            acc2.x += xv.z * wv.x; acc2.y += xv.z * wv.y; acc2.z += xv.z * wv.z; acc2.w += xv.z * wv.w;
            acc3.x += xv.w * wv.x; acc3.y += xv.w * wv.y; acc3.z += xv.w * wv.z; acc3.w += xv.w * wv.w;
        }
    }

    float4 bb = *(const float4*)&b[tx * 4];
    acc0.x += bb.x; acc0.y += bb.y; acc0.z += bb.z; acc0.w += bb.w;
    acc1.x += bb.x; acc1.y += bb.y; acc1.z += bb.z; acc1.w += bb.w;
    acc2.x += bb.x; acc2.y += bb.y; acc2.z += bb.z; acc2.w += bb.w;
    acc3.x += bb.x; acc3.y += bb.y; acc3.z += bb.z; acc3.w += bb.w;

    int nl = n0 + ty * 4;
    if (nl + 0 < Nn) *(float4*)&h[(size_t)(nl + 0) * 64 + tx * 4] = acc0;
    if (nl + 1 < Nn) *(float4*)&h[(size_t)(nl + 1) * 64 + tx * 4] = acc1;
    if (nl + 2 < Nn) *(float4*)&h[(size_t)(nl + 2) * 64 + tx * 4] = acc2;
    if (nl + 3 < Nn) *(float4*)&h[(size_t)(nl + 3) * 64 + tx * 4] = acc3;
}

// ============================================================
// Pooling (relu + sum/max per analytic graph ranges)
// ============================================================
__global__ void pool_kernel(const float* __restrict__ h, float* __restrict__ pooled)
{
    __shared__ float ss[4][64];
    __shared__ float sm[4][64];
    int g     = blockIdx.x;
    int f     = threadIdx.x & 63;
    int strip = threadIdx.x >> 6;
    int start = (g * Nn + Gg - 1) / Gg;
    int end   = ((g + 1) * Nn + Gg - 1) / Gg;

    float s = 0.f, m = 0.f;
    for (int n = start + strip; n < end; n += 4) {
        float v = fmaxf(__ldg(h + (size_t)n * 64 + f), 0.f);
        s += v;
        m = fmaxf(m, v);
    }
    ss[strip][f] = s;
    sm[strip][f] = m;
    __syncthreads();
    if (strip == 0) {
        s = ss[0][f] + ss[1][f] + ss[2][f] + ss[3][f];
        m = fmaxf(fmaxf(sm[0][f], sm[1][f]), fmaxf(sm[2][f], sm[3][f]));
        pooled[g * 128 + f]      = s;
        pooled[g * 128 + 64 + f] = m;
    }
}

// ============================================================
// Head: BN -> FC -> log_softmax
// ============================================================
__global__ void head_kernel(const float* __restrict__ pooled,
                            const float* __restrict__ gam,
                            const float* __restrict__ bet,
                            const float* __restrict__ mean,
                            const float* __restrict__ var,
                            const float* __restrict__ fw,
                            const float* __restrict__ fb,
                            float* __restrict__ out)
{
    int g    = blockIdx.x;
    int lane = threadIdx.x;

    float pn[4];
#pragma unroll
    for (int i = 0; i < 4; ++i) {
        int c = lane + 32 * i;
        float p = __ldg(pooled + g * 128 + c);
        float inv = 1.f / sqrtf(__ldg(var + c) + 1e-5f);
        pn[i] = (p - __ldg(mean + c)) * inv * __ldg(gam + c) + __ldg(bet + c);
    }

    float logits[6];
#pragma unroll
    for (int j = 0; j < 6; ++j) {
        float s = 0.f;
#pragma unroll
        for (int i = 0; i < 4; ++i)
            s += pn[i] * __ldg(fw + (lane + 32 * i) * 6 + j);
#pragma unroll
        for (int o = 16; o; o >>= 1)
            s += __shfl_xor_sync(0xffffffffu, s, o);
        logits[j] = s + __ldg(fb + j);
    }

    if (lane == 0) {
        float m = logits[0];
#pragma unroll
        for (int j = 1; j < 6; ++j) m = fmaxf(m, logits[j]);
        float se = 0.f;
#pragma unroll
        for (int j = 0; j < 6; ++j) se += expf(logits[j] - m);
        float lse = m + logf(se);
#pragma unroll
        for (int j = 0; j < 6; ++j) out[g * 6 + j] = logits[j] - lse;
    }
}

// ============================================================
extern "C" void kernel_launch(void* const* d_in, const int* in_sizes, int n_in,
                              void* d_out, int out_size)
{
    const float* x   = (const float*)d_in[0];
    const int*   ei  = (const int*)  d_in[1];
    const float* ea  = (const float*)d_in[2];
    const float* W1  = (const float*)d_in[4];
    const float* b1  = (const float*)d_in[5];
    const float* W2  = (const float*)d_in[6];
    const float* b2  = (const float*)d_in[7];
    const float* W3  = (const float*)d_in[8];
    const float* b3  = (const float*)d_in[9];
    const float* W4  = (const float*)d_in[10];
    const float* b4  = (const float*)d_in[11];
    const float* bng = (const float*)d_in[12];
    const float* bnb = (const float*)d_in[13];
    const float* bnm = (const float*)d_in[14];
    const float* bnv = (const float*)d_in[15];
    const float* fw  = (const float*)d_in[16];
    const float* fb  = (const float*)d_in[17];
    float* out = (float*)d_out;

    float *zb, *h0, *h1, *pl, *sea1p;
    int *cnt, *cur, *rp, *ssrc;
    float4* sea4p;
    cudaGetSymbolAddress((void**)&zb, g_z);
    cudaGetSymbolAddress((void**)&h0, g_h0);
    cudaGetSymbolAddress((void**)&h1, g_h1);
    cudaGetSymbolAddress((void**)&pl, g_pool);
    cudaGetSymbolAddress((void**)&cnt, g_cnt);
    cudaGetSymbolAddress((void**)&cur, g_cursor);
    cudaGetSymbolAddress((void**)&rp, g_rowptr);
    cudaGetSymbolAddress((void**)&ssrc, g_ssrc);
    cudaGetSymbolAddress((void**)&sea4p, g_sea4);
    cudaGetSymbolAddress((void**)&sea1p, g_sea1);

    const int EB = (Ee + 255) / 256;       // 6250
    const int GB = (Nn + 63) / 64;         // 782
    const int AB = (Nn + 7) / 8;           // 6250 (one warp per dst)

    // ---- counting sort of edges by dst -> CSR ----
    zero_cnt_kernel<<<(Nn + 255) / 256, 256>>>(cnt);
    hist_kernel<<<EB, 256>>>(ei, cnt);
    scan_kernel<<<1, 1024>>>(cnt, cur, rp);
    permute_kernel<<<EB, 256>>>(ei, ea, cur, ssrc, sea4p, sea1p);

    // ---- layer 1 (in: x [N,16], no relu) ----
    aggregate16_kernel<<<AB, 256>>>(rp, ssrc, sea4p, sea1p, x, zb);
    gemmsum_kernel<16><<<GB, 256>>>(zb, W1, b1, h0);
    // ---- layer 2 ----
    aggregate64_kernel<1><<<AB, 256>>>(rp, ssrc, sea4p, sea1p, h0, zb);
    gemmsum_kernel<64><<<GB, 256>>>(zb, W2, b2, h1);
    // ---- layer 3 ----
    aggregate64_kernel<1><<<AB, 256>>>(rp, ssrc, sea4p, sea1p, h1, zb);
    gemmsum_kernel<64><<<GB, 256>>>(zb, W3, b3, h0);
    // ---- layer 4 ----
    aggregate64_kernel<1><<<AB, 256>>>(rp, ssrc, sea4p, sea1p, h0, zb);
    gemmsum_kernel<64><<<GB, 256>>>(zb, W4, b4, h1);

    pool_kernel<<<Gg, 256>>>(h1, pl);
    head_kernel<<<Gg, 32>>>(pl, bng, bnb, bnm, bnv, fw, fb, out);
}